// round 1
// baseline (speedup 1.0000x reference)
#include <cuda_runtime.h>
#include <math.h>

#define B_ 64
#define T_ 256
#define C_ 384
#define H_ 6
#define D_ 64
#define K_ 384   // inner dim of both GEMMs (= C_)

// Scratch (allocation-free: __device__ globals)
__device__ float g_q[B_*H_*T_*D_];    // [B,H,T,D]
__device__ float g_k[B_*H_*T_*D_];
__device__ float g_v[B_*H_*T_*D_];
__device__ float g_att[B_*T_*C_];     // attention output, [B,T,C] with C = h*64+d

// ---------------------------------------------------------------------------
// Tiled SGEMM: C[M,N] = A[M,K_] * W[K_,N] + bias
// 128x128 block tile, BK=8, 256 threads, 8x8 per-thread micro tile.
// MODE 0: A = x, scatter output into g_q/g_k/g_v   (N = 1152)
// MODE 1: A = g_att, write out + bias              (N = 384)
// ---------------------------------------------------------------------------
template<int N, int MODE>
__global__ __launch_bounds__(256, 2) void gemm_kernel(const float* __restrict__ A,
                                                      const float* __restrict__ W,
                                                      const float* __restrict__ bias,
                                                      float* __restrict__ out) {
    __shared__ float As[8][128];   // transposed: As[k][m]
    __shared__ float Bs[8][128];   // Bs[k][n]

    const int tid = threadIdx.x;
    const int m0 = blockIdx.y * 128;
    const int n0 = blockIdx.x * 128;
    const int ty = tid >> 4;        // 0..15
    const int tx = tid & 15;        // 0..15

    const float* Ap = (MODE == 0) ? A : g_att;

    // global-load mapping
    const int arow  = tid >> 1;         // 0..127
    const int akseg = (tid & 1) << 2;   // 0 or 4
    const int brow  = tid >> 5;         // 0..7
    const int bcol  = (tid & 31) << 2;  // 0..124

    const float* aptr = Ap + (size_t)(m0 + arow) * K_ + akseg;
    const float* wptr = W + (size_t)brow * N + n0 + bcol;

    float acc[8][8] = {};

    float4 av = *(const float4*)(aptr);
    float4 bv = *(const float4*)(wptr);

    for (int k0 = 0; k0 < K_; k0 += 8) {
        __syncthreads();
        As[akseg + 0][arow] = av.x;
        As[akseg + 1][arow] = av.y;
        As[akseg + 2][arow] = av.z;
        As[akseg + 3][arow] = av.w;
        *(float4*)&Bs[brow][bcol] = bv;
        __syncthreads();
        if (k0 + 8 < K_) {
            av = *(const float4*)(aptr + k0 + 8);
            bv = *(const float4*)(wptr + (size_t)(k0 + 8) * N);
        }
        #pragma unroll
        for (int kk = 0; kk < 8; kk++) {
            float4 a0 = *(float4*)&As[kk][ty << 2];
            float4 a1 = *(float4*)&As[kk][64 + (ty << 2)];
            float4 b0 = *(float4*)&Bs[kk][tx << 2];
            float4 b1 = *(float4*)&Bs[kk][64 + (tx << 2)];
            float a[8] = {a0.x, a0.y, a0.z, a0.w, a1.x, a1.y, a1.z, a1.w};
            float b[8] = {b0.x, b0.y, b0.z, b0.w, b1.x, b1.y, b1.z, b1.w};
            #pragma unroll
            for (int i = 0; i < 8; i++)
                #pragma unroll
                for (int j = 0; j < 8; j++)
                    acc[i][j] += a[i] * b[j];
        }
    }

    // epilogue: bias + write (vectorized in groups of 4 columns)
    #pragma unroll
    for (int i = 0; i < 8; i++) {
        const int gm = m0 + ((i < 4) ? (ty * 4 + i) : (64 + ty * 4 + i - 4));
        #pragma unroll
        for (int jj = 0; jj < 2; jj++) {
            const int gnb = n0 + tx * 4 + jj * 64;
            float4 bb4 = *(const float4*)&bias[gnb];
            float4 v;
            v.x = acc[i][jj * 4 + 0] + bb4.x;
            v.y = acc[i][jj * 4 + 1] + bb4.y;
            v.z = acc[i][jj * 4 + 2] + bb4.z;
            v.w = acc[i][jj * 4 + 3] + bb4.w;
            if (MODE == 0) {
                const int which = gnb / C_;
                const int rem = gnb - which * C_;
                const int h = rem >> 6;
                const int d = rem & 63;
                const int bidx = gm >> 8;        // / T_
                const int tt = gm & 255;         // % T_
                float* dst = (which == 0) ? g_q : (which == 1) ? g_k : g_v;
                *(float4*)&dst[(((size_t)(bidx * H_ + h) << 8) + tt) * D_ + d] = v;
            } else {
                *(float4*)&out[(size_t)gm * N + gnb] = v;
            }
        }
    }
}

// ---------------------------------------------------------------------------
// Flash attention, fp32. grid = (T/64, B*H), 256 threads.
// Br = 64 queries/block, Bc = 32 keys/iter, online softmax.
// ---------------------------------------------------------------------------
__global__ __launch_bounds__(256, 2) void attn_kernel() {
    __shared__ float Qs[64][68];   // [d][i]  (transposed)
    __shared__ float Ks[64][36];   // [d][j]  (transposed)
    __shared__ float Vs[32][68];   // [j][d]
    __shared__ float Ss[64][36];   // [i][j]  scores -> probs
    __shared__ float m_s[64], l_s[64], sc_s[64];

    const int tid = threadIdx.x;
    const int qt = blockIdx.x;          // query tile
    const int bh = blockIdx.y;          // b*H + h
    const int ty = tid >> 4;            // 0..15
    const int tx = tid & 15;            // 0..15

    // load Q tile (64 x 64) transposed into Qs
    const float* qbase = g_q + ((size_t)bh * T_ + qt * 64) * D_;
    #pragma unroll
    for (int r = 0; r < 4; r++) {
        int f4 = tid + r * 256;              // 0..1023
        int i = f4 >> 4;
        int dseg = (f4 & 15) << 2;
        float4 v = *(const float4*)(qbase + i * D_ + dseg);
        Qs[dseg + 0][i] = v.x;
        Qs[dseg + 1][i] = v.y;
        Qs[dseg + 2][i] = v.z;
        Qs[dseg + 3][i] = v.w;
    }
    if (tid < 64) { m_s[tid] = -INFINITY; l_s[tid] = 0.f; }

    float O[4][4] = {};   // rows ty*4..+3, cols tx*4..+3

    const int nkt = (qt + 1) * 2;   // causal: key tiles 0..nkt-1
    for (int jt = 0; jt < nkt; jt++) {
        __syncthreads();   // previous iteration fully consumed smem
        // load K, V tiles (32 rows x 64)
        const float* kbase = g_k + ((size_t)bh * T_ + jt * 32) * D_;
        const float* vbase = g_v + ((size_t)bh * T_ + jt * 32) * D_;
        #pragma unroll
        for (int r = 0; r < 2; r++) {
            int f4 = tid + r * 256;          // 0..511
            int j = f4 >> 4;
            int dseg = (f4 & 15) << 2;
            float4 kv = *(const float4*)(kbase + j * D_ + dseg);
            Ks[dseg + 0][j] = kv.x;
            Ks[dseg + 1][j] = kv.y;
            Ks[dseg + 2][j] = kv.z;
            Ks[dseg + 3][j] = kv.w;
            float4 vv = *(const float4*)(vbase + j * D_ + dseg);
            *(float4*)&Vs[j][dseg] = vv;
        }
        __syncthreads();

        // S = Q K^T : rows ty*4..+3, cols tx*2..+1
        float s[4][2] = {};
        #pragma unroll
        for (int d = 0; d < 64; d++) {
            float4 a = *(float4*)&Qs[d][ty << 2];
            float b0 = Ks[d][tx * 2 + 0];
            float b1 = Ks[d][tx * 2 + 1];
            s[0][0] += a.x * b0;  s[0][1] += a.x * b1;
            s[1][0] += a.y * b0;  s[1][1] += a.y * b1;
            s[2][0] += a.z * b0;  s[2][1] += a.z * b1;
            s[3][0] += a.w * b0;  s[3][1] += a.w * b1;
        }
        #pragma unroll
        for (int r = 0; r < 4; r++)
            #pragma unroll
            for (int c = 0; c < 2; c++)
                Ss[ty * 4 + r][tx * 2 + c] = s[r][c] * 0.125f;  // D^-0.5
        __syncthreads();

        // online softmax: 4 threads per row, 8 cols each
        {
            const int row = tid >> 2;
            const int q = tid & 3;
            const int ig = qt * 64 + row;
            float vals[8];
            float mx = -INFINITY;
            #pragma unroll
            for (int c = 0; c < 8; c++) {
                int col = q * 8 + c;
                int jg = jt * 32 + col;
                float v = (jg <= ig) ? Ss[row][col] : -INFINITY;
                vals[c] = v;
                mx = fmaxf(mx, v);
            }
            mx = fmaxf(mx, __shfl_xor_sync(0xffffffffu, mx, 1));
            mx = fmaxf(mx, __shfl_xor_sync(0xffffffffu, mx, 2));
            const float m_old = m_s[row];
            const float m_new = fmaxf(m_old, mx);
            float sum = 0.f;
            #pragma unroll
            for (int c = 0; c < 8; c++) {
                float p = __expf(vals[c] - m_new);
                Ss[row][q * 8 + c] = p;
                sum += p;
            }
            sum += __shfl_xor_sync(0xffffffffu, sum, 1);
            sum += __shfl_xor_sync(0xffffffffu, sum, 2);
            const float scale = __expf(m_old - m_new);
            if (q == 0) {
                l_s[row] = l_s[row] * scale + sum;
                m_s[row] = m_new;
                sc_s[row] = scale;
            }
        }
        __syncthreads();

        // rescale O, then O += P V : rows ty*4..+3, cols tx*4..+3
        float sc[4];
        #pragma unroll
        for (int r = 0; r < 4; r++) sc[r] = sc_s[ty * 4 + r];
        #pragma unroll
        for (int r = 0; r < 4; r++)
            #pragma unroll
            for (int c = 0; c < 4; c++)
                O[r][c] *= sc[r];
        #pragma unroll
        for (int kk = 0; kk < 32; kk++) {
            float4 b = *(float4*)&Vs[kk][tx << 2];
            float p0 = Ss[ty * 4 + 0][kk];
            float p1 = Ss[ty * 4 + 1][kk];
            float p2 = Ss[ty * 4 + 2][kk];
            float p3 = Ss[ty * 4 + 3][kk];
            O[0][0] += p0 * b.x; O[0][1] += p0 * b.y; O[0][2] += p0 * b.z; O[0][3] += p0 * b.w;
            O[1][0] += p1 * b.x; O[1][1] += p1 * b.y; O[1][2] += p1 * b.z; O[1][3] += p1 * b.w;
            O[2][0] += p2 * b.x; O[2][1] += p2 * b.y; O[2][2] += p2 * b.z; O[2][3] += p2 * b.w;
            O[3][0] += p3 * b.x; O[3][1] += p3 * b.y; O[3][2] += p3 * b.z; O[3][3] += p3 * b.w;
        }
    }

    // final normalize + write to g_att [B,T,C], C index = h*64 + d
    const int b = bh / H_;
    const int h = bh - b * H_;
    #pragma unroll
    for (int r = 0; r < 4; r++) {
        const int row = ty * 4 + r;
        const float linv = 1.f / l_s[row];
        const int t = qt * 64 + row;
        float4 v;
        v.x = O[r][0] * linv;
        v.y = O[r][1] * linv;
        v.z = O[r][2] * linv;
        v.w = O[r][3] * linv;
        *(float4*)&g_att[((size_t)(b * T_ + t)) * C_ + h * 64 + (tx << 2)] = v;
    }
}

// ---------------------------------------------------------------------------
extern "C" void kernel_launch(void* const* d_in, const int* in_sizes, int n_in,
                              void* d_out, int out_size) {
    const float* x     = (const float*)d_in[0];
    const float* Wqkv  = (const float*)d_in[1];
    const float* bqkv  = (const float*)d_in[2];
    const float* Wproj = (const float*)d_in[3];
    const float* bproj = (const float*)d_in[4];
    float* out = (float*)d_out;

    // 1) QKV projection + scatter to [B,H,T,D]
    dim3 g1(3 * C_ / 128, (B_ * T_) / 128);   // (9, 128)
    gemm_kernel<3 * C_, 0><<<g1, 256>>>(x, Wqkv, bqkv, nullptr);

    // 2) causal flash attention -> g_att [B,T,C]
    dim3 g2(T_ / 64, B_ * H_);                // (4, 384)
    attn_kernel<<<g2, 256>>>();

    // 3) output projection
    dim3 g3(C_ / 128, (B_ * T_) / 128);       // (3, 128)
    gemm_kernel<C_, 1><<<g3, 256>>>(nullptr, Wproj, bproj, out);
}

// round 4
// speedup vs baseline: 1.5225x; 1.5225x over previous
#include <cuda_runtime.h>
#include <math.h>
#include <cstdint>

#define B_ 64
#define T_ 256
#define C_ 384
#define H_ 6
#define D_ 64
#define K_ 384

// ------------------------- scratch (no allocation) -------------------------
__device__ float g_q[B_*H_*T_*D_];
__device__ float g_k[B_*H_*T_*D_];
__device__ float g_v[B_*H_*T_*D_];
__device__ float g_att[B_*T_*C_];

// ------------------------- helpers -------------------------
__device__ __forceinline__ uint32_t f2tf(float f) {
    uint32_t r;
    asm("cvt.rna.tf32.f32 %0, %1;" : "=r"(r) : "f"(f));
    return r;
}
__device__ __forceinline__ void mma_tf32(float c[4], const uint32_t a[4], const uint32_t b[2]) {
    asm volatile(
        "mma.sync.aligned.m16n8k8.row.col.f32.tf32.tf32.f32 "
        "{%0,%1,%2,%3}, {%4,%5,%6,%7}, {%8,%9}, {%0,%1,%2,%3};"
        : "+f"(c[0]), "+f"(c[1]), "+f"(c[2]), "+f"(c[3])
        : "r"(a[0]), "r"(a[1]), "r"(a[2]), "r"(a[3]), "r"(b[0]), "r"(b[1]));
}

// ---------------------------------------------------------------------------
// tf32 tensor-core GEMM: C[M,N] = A[M,K_] * W[K_,N] + bias
// 128x128 block tile, BK=16, 256 threads (8 warps, 2x4), warp tile 64x32.
// MODE 0: scatter output into g_q/g_k/g_v (N=1152). MODE 1: write out (N=384).
// ---------------------------------------------------------------------------
#define APITCH 20
#define BPITCH 132

template<int N, int MODE>
__global__ __launch_bounds__(256) void gemm_mma(const float* __restrict__ A,
                                                const float* __restrict__ W,
                                                const float* __restrict__ bias,
                                                float* __restrict__ out) {
    __shared__ uint32_t As[128][APITCH];   // [m][k], BK=16 + pad
    __shared__ uint32_t Bs[16][BPITCH];    // [k][n], 128 + pad

    const int tid = threadIdx.x;
    const int wid = tid >> 5;
    const int lane = tid & 31;
    const int m0 = blockIdx.y * 128;
    const int n0 = blockIdx.x * 128;
    const int wm = (wid & 1) * 64;        // warp m-offset within block
    const int wn = (wid >> 1) * 32;       // warp n-offset within block

    const float* Ap = (MODE == 0) ? A : g_att;

    // global load mapping
    const int arow = tid >> 2;            // 0..63 (and +64)
    const int acs  = (tid & 3) << 2;      // col seg 0/4/8/12
    const int brow = tid >> 5;            // 0..7 (and +8)
    const int bcs  = (tid & 31) << 2;     // 0..124

    const float* aptr = Ap + (size_t)(m0 + arow) * K_ + acs;
    const float* bptr = W + (size_t)brow * N + n0 + bcs;

    float acc[4][4][4] = {};              // [mt][nt][reg]

    float4 av0 = *(const float4*)(aptr);
    float4 av1 = *(const float4*)(aptr + (size_t)64 * K_);
    float4 bv0 = *(const float4*)(bptr);
    float4 bv1 = *(const float4*)(bptr + (size_t)8 * N);

    const int NCH = K_ / 16;              // 24
    for (int kc = 0; kc < NCH; kc++) {
        __syncthreads();
        As[arow][acs + 0] = f2tf(av0.x);
        As[arow][acs + 1] = f2tf(av0.y);
        As[arow][acs + 2] = f2tf(av0.z);
        As[arow][acs + 3] = f2tf(av0.w);
        As[arow + 64][acs + 0] = f2tf(av1.x);
        As[arow + 64][acs + 1] = f2tf(av1.y);
        As[arow + 64][acs + 2] = f2tf(av1.z);
        As[arow + 64][acs + 3] = f2tf(av1.w);
        Bs[brow][bcs + 0] = f2tf(bv0.x);
        Bs[brow][bcs + 1] = f2tf(bv0.y);
        Bs[brow][bcs + 2] = f2tf(bv0.z);
        Bs[brow][bcs + 3] = f2tf(bv0.w);
        Bs[brow + 8][bcs + 0] = f2tf(bv1.x);
        Bs[brow + 8][bcs + 1] = f2tf(bv1.y);
        Bs[brow + 8][bcs + 2] = f2tf(bv1.z);
        Bs[brow + 8][bcs + 3] = f2tf(bv1.w);
        __syncthreads();
        if (kc + 1 < NCH) {
            const int k0 = (kc + 1) * 16;
            av0 = *(const float4*)(aptr + k0);
            av1 = *(const float4*)(aptr + (size_t)64 * K_ + k0);
            bv0 = *(const float4*)(bptr + (size_t)k0 * N);
            bv1 = *(const float4*)(bptr + (size_t)(k0 + 8) * N);
        }

        #pragma unroll
        for (int ks = 0; ks < 2; ks++) {
            const int k = ks * 8;
            const int r = lane >> 2;      // 0..7
            const int q = lane & 3;       // 0..3
            uint32_t af[4][4];
            #pragma unroll
            for (int mt = 0; mt < 4; mt++) {
                const int mr = wm + mt * 16 + r;
                af[mt][0] = As[mr][k + q];
                af[mt][1] = As[mr + 8][k + q];
                af[mt][2] = As[mr][k + q + 4];
                af[mt][3] = As[mr + 8][k + q + 4];
            }
            uint32_t bf[4][2];
            #pragma unroll
            for (int nt = 0; nt < 4; nt++) {
                const int nc = wn + nt * 8 + r;
                bf[nt][0] = Bs[k + q][nc];
                bf[nt][1] = Bs[k + q + 4][nc];
            }
            #pragma unroll
            for (int mt = 0; mt < 4; mt++)
                #pragma unroll
                for (int nt = 0; nt < 4; nt++)
                    mma_tf32(acc[mt][nt], af[mt], bf[nt]);
        }
    }

    // ---- epilogue: bias + store (float2 pairs per fragment row) ----
    const int r = lane >> 2;
    const int q = lane & 3;
    #pragma unroll
    for (int mt = 0; mt < 4; mt++) {
        #pragma unroll
        for (int nt = 0; nt < 4; nt++) {
            const int row0 = m0 + wm + mt * 16 + r;
            const int col = n0 + wn + nt * 8 + q * 2;
            const float b0 = bias[col], b1 = bias[col + 1];
            float2 v0 = {acc[mt][nt][0] + b0, acc[mt][nt][1] + b1};
            float2 v1 = {acc[mt][nt][2] + b0, acc[mt][nt][3] + b1};
            if (MODE == 0) {
                const int which = n0 / C_;              // block fits in one of q/k/v
                const int rem = col - which * C_;
                const int h = rem >> 6, d = rem & 63;
                float* qkv = (which == 0) ? g_q : (which == 1) ? g_k : g_v;
                const int b0i = row0 >> 8, t0 = row0 & 255;
                *(float2*)&qkv[(((size_t)(b0i * H_ + h) * T_) + t0) * D_ + d] = v0;
                const int row1 = row0 + 8;
                const int b1i = row1 >> 8, t1 = row1 & 255;
                *(float2*)&qkv[(((size_t)(b1i * H_ + h) * T_) + t1) * D_ + d] = v1;
            } else {
                *(float2*)&out[(size_t)row0 * N + col] = v0;
                *(float2*)&out[(size_t)(row0 + 8) * N + col] = v1;
            }
        }
    }
}

// ---------------------------------------------------------------------------
// Flash attention, fp32 (round-1 version, known correct).
// grid = (T/64, B*H), 256 threads. Br=64, Bc=32, online softmax.
// ---------------------------------------------------------------------------
__global__ __launch_bounds__(256, 2) void attn_kernel() {
    __shared__ float Qs[64][68];
    __shared__ float Ks[64][36];
    __shared__ float Vs[32][68];
    __shared__ float Ss[64][36];
    __shared__ float m_s[64], l_s[64], sc_s[64];

    const int tid = threadIdx.x;
    const int qt = blockIdx.x;
    const int bh = blockIdx.y;
    const int ty = tid >> 4;
    const int tx = tid & 15;

    const float* qbase = g_q + ((size_t)bh * T_ + qt * 64) * D_;
    #pragma unroll
    for (int r = 0; r < 4; r++) {
        int f4 = tid + r * 256;
        int i = f4 >> 4;
        int dseg = (f4 & 15) << 2;
        float4 v = *(const float4*)(qbase + i * D_ + dseg);
        Qs[dseg + 0][i] = v.x;
        Qs[dseg + 1][i] = v.y;
        Qs[dseg + 2][i] = v.z;
        Qs[dseg + 3][i] = v.w;
    }
    if (tid < 64) { m_s[tid] = -INFINITY; l_s[tid] = 0.f; }

    float O[4][4] = {};

    const int nkt = (qt + 1) * 2;
    for (int jt = 0; jt < nkt; jt++) {
        __syncthreads();
        const float* kbase = g_k + ((size_t)bh * T_ + jt * 32) * D_;
        const float* vbase = g_v + ((size_t)bh * T_ + jt * 32) * D_;
        #pragma unroll
        for (int r = 0; r < 2; r++) {
            int f4 = tid + r * 256;
            int j = f4 >> 4;
            int dseg = (f4 & 15) << 2;
            float4 kv = *(const float4*)(kbase + j * D_ + dseg);
            Ks[dseg + 0][j] = kv.x;
            Ks[dseg + 1][j] = kv.y;
            Ks[dseg + 2][j] = kv.z;
            Ks[dseg + 3][j] = kv.w;
            float4 vv = *(const float4*)(vbase + j * D_ + dseg);
            *(float4*)&Vs[j][dseg] = vv;
        }
        __syncthreads();

        float s[4][2] = {};
        #pragma unroll
        for (int d = 0; d < 64; d++) {
            float4 a = *(float4*)&Qs[d][ty << 2];
            float b0 = Ks[d][tx * 2 + 0];
            float b1 = Ks[d][tx * 2 + 1];
            s[0][0] += a.x * b0;  s[0][1] += a.x * b1;
            s[1][0] += a.y * b0;  s[1][1] += a.y * b1;
            s[2][0] += a.z * b0;  s[2][1] += a.z * b1;
            s[3][0] += a.w * b0;  s[3][1] += a.w * b1;
        }
        #pragma unroll
        for (int r = 0; r < 4; r++)
            #pragma unroll
            for (int c = 0; c < 2; c++)
                Ss[ty * 4 + r][tx * 2 + c] = s[r][c] * 0.125f;
        __syncthreads();

        {
            const int row = tid >> 2;
            const int q = tid & 3;
            const int ig = qt * 64 + row;
            float vals[8];
            float mx = -INFINITY;
            #pragma unroll
            for (int c = 0; c < 8; c++) {
                int col = q * 8 + c;
                int jg = jt * 32 + col;
                float v = (jg <= ig) ? Ss[row][col] : -INFINITY;
                vals[c] = v;
                mx = fmaxf(mx, v);
            }
            mx = fmaxf(mx, __shfl_xor_sync(0xffffffffu, mx, 1));
            mx = fmaxf(mx, __shfl_xor_sync(0xffffffffu, mx, 2));
            const float m_old = m_s[row];
            const float m_new = fmaxf(m_old, mx);
            float sum = 0.f;
            #pragma unroll
            for (int c = 0; c < 8; c++) {
                float p = __expf(vals[c] - m_new);
                Ss[row][q * 8 + c] = p;
                sum += p;
            }
            sum += __shfl_xor_sync(0xffffffffu, sum, 1);
            sum += __shfl_xor_sync(0xffffffffu, sum, 2);
            const float scale = __expf(m_old - m_new);
            if (q == 0) {
                l_s[row] = l_s[row] * scale + sum;
                m_s[row] = m_new;
                sc_s[row] = scale;
            }
        }
        __syncthreads();

        float sc[4];
        #pragma unroll
        for (int r = 0; r < 4; r++) sc[r] = sc_s[ty * 4 + r];
        #pragma unroll
        for (int r = 0; r < 4; r++)
            #pragma unroll
            for (int c = 0; c < 4; c++)
                O[r][c] *= sc[r];
        #pragma unroll
        for (int kk = 0; kk < 32; kk++) {
            float4 b = *(float4*)&Vs[kk][tx << 2];
            float p0 = Ss[ty * 4 + 0][kk];
            float p1 = Ss[ty * 4 + 1][kk];
            float p2 = Ss[ty * 4 + 2][kk];
            float p3 = Ss[ty * 4 + 3][kk];
            O[0][0] += p0 * b.x; O[0][1] += p0 * b.y; O[0][2] += p0 * b.z; O[0][3] += p0 * b.w;
            O[1][0] += p1 * b.x; O[1][1] += p1 * b.y; O[1][2] += p1 * b.z; O[1][3] += p1 * b.w;
            O[2][0] += p2 * b.x; O[2][1] += p2 * b.y; O[2][2] += p2 * b.z; O[2][3] += p2 * b.w;
            O[3][0] += p3 * b.x; O[3][1] += p3 * b.y; O[3][2] += p3 * b.z; O[3][3] += p3 * b.w;
        }
    }

    const int b = bh / H_;
    const int h = bh - b * H_;
    #pragma unroll
    for (int r = 0; r < 4; r++) {
        const int row = ty * 4 + r;
        const float linv = 1.f / l_s[row];
        const int t = qt * 64 + row;
        float4 v;
        v.x = O[r][0] * linv;
        v.y = O[r][1] * linv;
        v.z = O[r][2] * linv;
        v.w = O[r][3] * linv;
        *(float4*)&g_att[((size_t)(b * T_ + t)) * C_ + h * 64 + (tx << 2)] = v;
    }
}

// ---------------------------------------------------------------------------
extern "C" void kernel_launch(void* const* d_in, const int* in_sizes, int n_in,
                              void* d_out, int out_size) {
    const float* x     = (const float*)d_in[0];
    const float* Wqkv  = (const float*)d_in[1];
    const float* bqkv  = (const float*)d_in[2];
    const float* Wproj = (const float*)d_in[3];
    const float* bproj = (const float*)d_in[4];
    float* out = (float*)d_out;

    // 1) QKV projection (tf32 tensor cores) + scatter to [B,H,T,D]
    gemm_mma<3 * C_, 0><<<dim3(3 * C_ / 128, (B_ * T_) / 128), 256>>>(x, Wqkv, bqkv, nullptr);

    // 2) causal flash attention -> g_att
    attn_kernel<<<dim3(T_ / 64, B_ * H_), 256>>>();

    // 3) output projection (tf32 tensor cores)
    gemm_mma<C_, 1><<<dim3(C_ / 128, (B_ * T_) / 128), 256>>>(nullptr, Wproj, bproj, out);
}

// round 6
// speedup vs baseline: 1.6446x; 1.0802x over previous
#include <cuda_runtime.h>
#include <math.h>
#include <cstdint>

#define B_ 64
#define T_ 256
#define C_ 384
#define H_ 6
#define D_ 64
#define K_ 384
#define M_TOT (B_*T_)   // 16384

// ------------------------- scratch (no allocation) -------------------------
__device__ float g_q[B_*H_*T_*D_];
__device__ float g_k[B_*H_*T_*D_];
__device__ float g_v[B_*H_*T_*D_];
__device__ uint32_t g_att[M_TOT*C_];   // attention out, tf32 bits, perm-k layout
__device__ uint32_t g_xc[M_TOT*K_];    // x as tf32 bits, perm-k layout
__device__ uint32_t g_wq[3*C_*K_];     // Wqkv^T: [n][perm(k)]
__device__ uint32_t g_wp[C_*K_];       // Wproj^T: [n][perm(k)]

// ------------------------- helpers -------------------------
__device__ __forceinline__ uint32_t f2tf(float f) {
    uint32_t r;
    asm("cvt.rna.tf32.f32 %0, %1;" : "=r"(r) : "f"(f));
    return r;
}
__device__ __forceinline__ void mma_tf32(float c[4], const uint32_t a[4], uint32_t b0, uint32_t b1) {
    asm volatile(
        "mma.sync.aligned.m16n8k8.row.col.f32.tf32.tf32.f32 "
        "{%0,%1,%2,%3}, {%4,%5,%6,%7}, {%8,%9}, {%0,%1,%2,%3};"
        : "+f"(c[0]), "+f"(c[1]), "+f"(c[2]), "+f"(c[3])
        : "r"(a[0]), "r"(a[1]), "r"(a[2]), "r"(a[3]), "r"(b0), "r"(b1));
}
#define CP16(dst, src) asm volatile("cp.async.cg.shared.global [%0], [%1], 16;" :: "r"(dst), "l"(src) : "memory")
#define CP_COMMIT()    asm volatile("cp.async.commit_group;" ::: "memory")
#define CP_WAIT1()     asm volatile("cp.async.wait_group 1;" ::: "memory")
#define CP_WAIT0()     asm volatile("cp.async.wait_group 0;" ::: "memory")

__device__ __forceinline__ uint32_t smem_u32(const void* p) {
    uint32_t a;
    asm("{ .reg .u64 t; cvta.to.shared.u64 t, %1; cvt.u32.u64 %0, t; }" : "=r"(a) : "l"(p));
    return a;
}
// perm within group of 8: pos(c) = (c&~7) | ((c&3)<<1) | ((c>>2)&1)
__device__ __forceinline__ int perm8(int c) {
    return (c & ~7) | (((c & 3) << 1) | ((c >> 2) & 1));
}

// ------------------------- conversion kernels -------------------------
// x[m][k] -> g_xc[m][perm(k)] (tf32 bits). One group of 8 per thread.
__global__ __launch_bounds__(256) void conv_x(const float* __restrict__ x) {
    const int gi = blockIdx.x * 256 + threadIdx.x;     // group index
    const size_t base = (size_t)gi * 8;
    float4 v0 = *(const float4*)(x + base);
    float4 v1 = *(const float4*)(x + base + 4);
    uint32_t* o = g_xc + base;
    o[0] = f2tf(v0.x); o[2] = f2tf(v0.y); o[4] = f2tf(v0.z); o[6] = f2tf(v0.w);
    o[1] = f2tf(v1.x); o[3] = f2tf(v1.y); o[5] = f2tf(v1.z); o[7] = f2tf(v1.w);
}

// W[k][n] -> out[n][perm(k)] (tf32 bits), 32x32 tile transpose
template<int WHICH>
__global__ void conv_w(const float* __restrict__ W, int N) {
    __shared__ float t[32][33];
    uint32_t* out = (WHICH == 0) ? g_wq : g_wp;
    const int nx = blockIdx.x * 32, kx = blockIdx.y * 32;
    const int x = threadIdx.x, y = threadIdx.y;
    #pragma unroll
    for (int i = y; i < 32; i += 8) t[i][x] = W[(size_t)(kx + i) * N + nx + x];
    __syncthreads();
    const int pk = kx + perm8(x);
    #pragma unroll
    for (int i = y; i < 32; i += 8) out[(size_t)(nx + i) * K_ + pk] = f2tf(t[x][i]);
}

// ---------------------------------------------------------------------------
// tf32 MMA GEMM with cp.async 3-stage pipeline.
// C[M,N] = A[M,K_] * W + bias. 128x128 tile, BK=16, 256 thr (8 warps 2x4).
// A and B both pre-converted tf32, perm-k, K-major. Smem pitch 20 u32.
// MODE 0: A=g_xc, B=g_wq, scatter to g_q/g_k/g_v.  MODE 1: A=g_att, B=g_wp.
// ---------------------------------------------------------------------------
#define GP 20
#define STG_BYTES (2 * 128 * GP * 4)   // 20480: A(10240) + B(10240)
#define GEMM_SMEM (3 * STG_BYTES)      // 61440

template<int N, int MODE>
__global__ __launch_bounds__(256) void gemm_tc(const float* __restrict__ bias,
                                               float* __restrict__ out) {
    extern __shared__ char smem[];
    const uint32_t sb = smem_u32(smem);
    const uint32_t* sm = (const uint32_t*)smem;

    const int tid = threadIdx.x;
    const int wid = tid >> 5;
    const int lane = tid & 31;
    const int r = lane >> 2, q = lane & 3;
    const int m0 = blockIdx.y * 128;
    const int n0 = blockIdx.x * 128;
    const int wm = (wid & 1) * 64;
    const int wn = (wid >> 1) * 32;

    const uint32_t* Ap = (MODE == 0) ? g_xc : g_att;
    const uint32_t* Bp = (MODE == 0) ? g_wq : g_wp;

    // cp.async mapping: 2 chunks A + 2 chunks B per thread per stage
    const int crow0 = tid >> 2, cseg0 = tid & 3;            // chunk tid
    const int crow1 = (tid + 256) >> 2, cseg1 = (tid + 256) & 3;

    auto load_stage = [&](int kc, int st) {
        const int k0 = kc * 16;
        const uint32_t sA = sb + st * STG_BYTES;
        const uint32_t sB = sA + 128 * GP * 4;
        CP16(sA + crow0 * (GP * 4) + cseg0 * 16, Ap + (size_t)(m0 + crow0) * K_ + k0 + cseg0 * 4);
        CP16(sA + crow1 * (GP * 4) + cseg1 * 16, Ap + (size_t)(m0 + crow1) * K_ + k0 + cseg1 * 4);
        CP16(sB + crow0 * (GP * 4) + cseg0 * 16, Bp + (size_t)(n0 + crow0) * K_ + k0 + cseg0 * 4);
        CP16(sB + crow1 * (GP * 4) + cseg1 * 16, Bp + (size_t)(n0 + crow1) * K_ + k0 + cseg1 * 4);
        CP_COMMIT();
    };

    float acc[4][4][4] = {};

    load_stage(0, 0);
    load_stage(1, 1);

    const int NCH = K_ / 16;   // 24
    for (int kc = 0; kc < NCH; kc++) {
        const int st = kc % 3;
        if (kc < NCH - 1) CP_WAIT1(); else CP_WAIT0();
        __syncthreads();
        if (kc + 2 < NCH) load_stage(kc + 2, (kc + 2) % 3);

        const uint32_t* As = sm + st * (STG_BYTES / 4);
        const uint32_t* Bs = As + 128 * GP;
        #pragma unroll
        for (int ks = 0; ks < 2; ks++) {
            const int koff = ks * 8 + 2 * q;
            uint32_t af[4][4];
            #pragma unroll
            for (int mt = 0; mt < 4; mt++) {
                const int mr = wm + mt * 16 + r;
                uint2 a0 = *(const uint2*)&As[mr * GP + koff];
                uint2 a1 = *(const uint2*)&As[(mr + 8) * GP + koff];
                af[mt][0] = a0.x; af[mt][1] = a1.x; af[mt][2] = a0.y; af[mt][3] = a1.y;
            }
            uint2 bf[4];
            #pragma unroll
            for (int nt = 0; nt < 4; nt++)
                bf[nt] = *(const uint2*)&Bs[(wn + nt * 8 + r) * GP + koff];
            #pragma unroll
            for (int mt = 0; mt < 4; mt++)
                #pragma unroll
                for (int nt = 0; nt < 4; nt++)
                    mma_tf32(acc[mt][nt], af[mt], bf[nt].x, bf[nt].y);
        }
    }

    // ---- epilogue: bias + store ----
    #pragma unroll
    for (int mt = 0; mt < 4; mt++) {
        #pragma unroll
        for (int nt = 0; nt < 4; nt++) {
            const int row0 = m0 + wm + mt * 16 + r;
            const int col = n0 + wn + nt * 8 + q * 2;
            const float b0 = bias[col], b1 = bias[col + 1];
            float2 v0 = {acc[mt][nt][0] + b0, acc[mt][nt][1] + b1};
            float2 v1 = {acc[mt][nt][2] + b0, acc[mt][nt][3] + b1};
            if (MODE == 0) {
                const int which = n0 / C_;
                const int rem = col - which * C_;
                const int h = rem >> 6, d = rem & 63;
                float* qkv = (which == 0) ? g_q : (which == 1) ? g_k : g_v;
                const int b0i = row0 >> 8, t0 = row0 & 255;
                *(float2*)&qkv[(((size_t)(b0i * H_ + h) * T_) + t0) * D_ + d] = v0;
                const int row1 = row0 + 8;
                const int b1i = row1 >> 8, t1 = row1 & 255;
                *(float2*)&qkv[(((size_t)(b1i * H_ + h) * T_) + t1) * D_ + d] = v1;
            } else {
                *(float2*)&out[(size_t)row0 * N + col] = v0;
                *(float2*)&out[(size_t)(row0 + 8) * N + col] = v1;
            }
        }
    }
}

// ---------------------------------------------------------------------------
// Flash attention with tf32 mma. grid=(T/64, B*H), 128 threads (4 warps).
// Br=64, Bc=64. Warp w owns query rows w*16..w*16+15. P via smem (tf32).
// Smem (u32): Qs[64][68], Ks[64][68], Ps[64][68], Vt[64][66]
// ---------------------------------------------------------------------------
#define QP 68
#define VP 66
#define OQ 0
#define OKs (64 * QP)
#define OPs (2 * 64 * QP)
#define OVt (3 * 64 * QP)
#define ATT_SMEM ((3 * 64 * QP + 64 * VP) * 4)   // 69120 bytes

__global__ __launch_bounds__(128) void attn_mma() {
    extern __shared__ char smem[];
    uint32_t* Qs = (uint32_t*)smem + OQ;
    uint32_t* Ks = (uint32_t*)smem + OKs;
    uint32_t* Ps = (uint32_t*)smem + OPs;
    uint32_t* Vt = (uint32_t*)smem + OVt;

    const int tid = threadIdx.x;
    const int w = tid >> 5;
    const int lane = tid & 31;
    const int r = lane >> 2, q = lane & 3;
    const int qt = blockIdx.x;
    const int bh = blockIdx.y;
    const int wrow = w * 16;
    const int pc0 = ((q & 1) << 2) | (q >> 1);   // perm position of col 2q in group

    // ---- load Q tile (64x64) -> Qs[row][perm(d)], tf32 ----
    const float* qbase = g_q + ((size_t)bh * T_ + qt * 64) * D_;
    #pragma unroll
    for (int i = 0; i < 8; i++) {
        const int f4 = tid + i * 128;
        const int row = f4 >> 4, ds = (f4 & 15) << 2;
        float4 v = *(const float4*)(qbase + row * D_ + ds);
        const int base = row * QP + (ds & ~7) + ((ds & 4) >> 2);
        Qs[base + 0] = f2tf(v.x); Qs[base + 2] = f2tf(v.y);
        Qs[base + 4] = f2tf(v.z); Qs[base + 6] = f2tf(v.w);
    }

    float m0 = -INFINITY, m1 = -INFINITY, l0 = 0.f, l1 = 0.f;
    float Oacc[8][4] = {};

    for (int jt = 0; jt <= qt; jt++) {
        __syncthreads();   // all warps done with prev Ks/Vt (and Q stores visible)
        // ---- load K tile -> Ks[key][perm(d)], V tile -> Vt[d][perm(key)] ----
        const float* kbase = g_k + ((size_t)bh * T_ + jt * 64) * D_;
        const float* vbase = g_v + ((size_t)bh * T_ + jt * 64) * D_;
        #pragma unroll
        for (int i = 0; i < 8; i++) {
            const int f4 = tid + i * 128;
            const int row = f4 >> 4, ds = (f4 & 15) << 2;
            float4 kv = *(const float4*)(kbase + row * D_ + ds);
            const int base = row * QP + (ds & ~7) + ((ds & 4) >> 2);
            Ks[base + 0] = f2tf(kv.x); Ks[base + 2] = f2tf(kv.y);
            Ks[base + 4] = f2tf(kv.z); Ks[base + 6] = f2tf(kv.w);
            float4 vv = *(const float4*)(vbase + row * D_ + ds);
            const int pj = perm8(row);
            Vt[(ds + 0) * VP + pj] = f2tf(vv.x);
            Vt[(ds + 1) * VP + pj] = f2tf(vv.y);
            Vt[(ds + 2) * VP + pj] = f2tf(vv.z);
            Vt[(ds + 3) * VP + pj] = f2tf(vv.w);
        }
        __syncthreads();

        // ---- S = Q K^T (warp rows wrow..wrow+15, cols 0..63) ----
        float S[8][4] = {};
        #pragma unroll
        for (int ks = 0; ks < 8; ks++) {
            const int koff = ks * 8 + 2 * q;
            uint2 a0 = *(const uint2*)&Qs[(wrow + r) * QP + koff];
            uint2 a1 = *(const uint2*)&Qs[(wrow + r + 8) * QP + koff];
            uint32_t af[4] = {a0.x, a1.x, a0.y, a1.y};
            #pragma unroll
            for (int nt = 0; nt < 8; nt++) {
                uint2 b = *(const uint2*)&Ks[(nt * 8 + r) * QP + koff];
                mma_tf32(S[nt], af, b.x, b.y);
            }
        }

        // ---- scale + causal mask ----
        #pragma unroll
        for (int nt = 0; nt < 8; nt++)
            #pragma unroll
            for (int c = 0; c < 4; c++)
                S[nt][c] *= 0.125f;
        if (jt == qt) {
            const int ir0 = wrow + r, ir1 = wrow + r + 8;
            #pragma unroll
            for (int nt = 0; nt < 8; nt++) {
                const int jc = nt * 8 + 2 * q;
                if (jc > ir0)     S[nt][0] = -INFINITY;
                if (jc + 1 > ir0) S[nt][1] = -INFINITY;
                if (jc > ir1)     S[nt][2] = -INFINITY;
                if (jc + 1 > ir1) S[nt][3] = -INFINITY;
            }
        }

        // ---- online softmax (rows r and r+8 of warp tile) ----
        float mx0 = -INFINITY, mx1 = -INFINITY;
        #pragma unroll
        for (int nt = 0; nt < 8; nt++) {
            mx0 = fmaxf(mx0, fmaxf(S[nt][0], S[nt][1]));
            mx1 = fmaxf(mx1, fmaxf(S[nt][2], S[nt][3]));
        }
        mx0 = fmaxf(mx0, __shfl_xor_sync(0xffffffffu, mx0, 1));
        mx0 = fmaxf(mx0, __shfl_xor_sync(0xffffffffu, mx0, 2));
        mx1 = fmaxf(mx1, __shfl_xor_sync(0xffffffffu, mx1, 1));
        mx1 = fmaxf(mx1, __shfl_xor_sync(0xffffffffu, mx1, 2));
        const float mn0 = fmaxf(m0, mx0), mn1 = fmaxf(m1, mx1);
        const float al0 = __expf(m0 - mn0), al1 = __expf(m1 - mn1);
        float s0 = 0.f, s1 = 0.f;
        #pragma unroll
        for (int nt = 0; nt < 8; nt++) {
            float p0 = __expf(S[nt][0] - mn0);
            float p1 = __expf(S[nt][1] - mn0);
            float p2 = __expf(S[nt][2] - mn1);
            float p3 = __expf(S[nt][3] - mn1);
            s0 += p0 + p1; s1 += p2 + p3;
            const int b0 = (wrow + r) * QP + nt * 8;
            const int b1 = (wrow + r + 8) * QP + nt * 8;
            Ps[b0 + pc0] = f2tf(p0); Ps[b0 + pc0 + 2] = f2tf(p1);
            Ps[b1 + pc0] = f2tf(p2); Ps[b1 + pc0 + 2] = f2tf(p3);
        }
        s0 += __shfl_xor_sync(0xffffffffu, s0, 1);
        s0 += __shfl_xor_sync(0xffffffffu, s0, 2);
        s1 += __shfl_xor_sync(0xffffffffu, s1, 1);
        s1 += __shfl_xor_sync(0xffffffffu, s1, 2);
        l0 = l0 * al0 + s0; l1 = l1 * al1 + s1;
        m0 = mn0; m1 = mn1;
        #pragma unroll
        for (int nt = 0; nt < 8; nt++) {
            Oacc[nt][0] *= al0; Oacc[nt][1] *= al0;
            Oacc[nt][2] *= al1; Oacc[nt][3] *= al1;
        }
        __syncwarp();

        // ---- O += P V  (A = Ps rows of this warp, B = Vt) ----
        #pragma unroll
        for (int ks = 0; ks < 8; ks++) {
            const int koff = ks * 8 + 2 * q;
            uint2 a0 = *(const uint2*)&Ps[(wrow + r) * QP + koff];
            uint2 a1 = *(const uint2*)&Ps[(wrow + r + 8) * QP + koff];
            uint32_t af[4] = {a0.x, a1.x, a0.y, a1.y};
            #pragma unroll
            for (int nt = 0; nt < 8; nt++) {
                uint2 b = *(const uint2*)&Vt[(nt * 8 + r) * VP + koff];
                mma_tf32(Oacc[nt], af, b.x, b.y);
            }
        }
    }

    // ---- epilogue: normalize, write g_att as tf32 bits, perm over C ----
    const float li0 = 1.f / l0, li1 = 1.f / l1;
    const int b = bh / H_;
    const int h = bh - b * H_;
    const int row0 = qt * 64 + wrow + r;
    const int row1 = row0 + 8;
    uint32_t* o0 = g_att + ((size_t)(b * T_) + row0) * C_ + h * 64;
    uint32_t* o1 = g_att + ((size_t)(b * T_) + row1) * C_ + h * 64;
    #pragma unroll
    for (int nt = 0; nt < 8; nt++) {
        const int p = nt * 8 + pc0;
        o0[p]     = f2tf(Oacc[nt][0] * li0);
        o0[p + 2] = f2tf(Oacc[nt][1] * li0);
        o1[p]     = f2tf(Oacc[nt][2] * li1);
        o1[p + 2] = f2tf(Oacc[nt][3] * li1);
    }
}

// ---------------------------------------------------------------------------
extern "C" void kernel_launch(void* const* d_in, const int* in_sizes, int n_in,
                              void* d_out, int out_size) {
    const float* x     = (const float*)d_in[0];
    const float* Wqkv  = (const float*)d_in[1];
    const float* bqkv  = (const float*)d_in[2];
    const float* Wproj = (const float*)d_in[3];
    const float* bproj = (const float*)d_in[4];
    float* out = (float*)d_out;

    cudaFuncSetAttribute(gemm_tc<3 * C_, 0>, cudaFuncAttributeMaxDynamicSharedMemorySize, GEMM_SMEM);
    cudaFuncSetAttribute(gemm_tc<C_, 1>,     cudaFuncAttributeMaxDynamicSharedMemorySize, GEMM_SMEM);
    cudaFuncSetAttribute(attn_mma,           cudaFuncAttributeMaxDynamicSharedMemorySize, ATT_SMEM);

    // 0) convert inputs to tf32 perm-k layouts
    conv_x<<<M_TOT * K_ / 8 / 256, 256>>>(x);
    conv_w<0><<<dim3(3 * C_ / 32, K_ / 32), dim3(32, 8)>>>(Wqkv, 3 * C_);
    conv_w<1><<<dim3(C_ / 32, K_ / 32), dim3(32, 8)>>>(Wproj, C_);

    // 1) QKV projection -> g_q/g_k/g_v
    gemm_tc<3 * C_, 0><<<dim3(3 * C_ / 128, M_TOT / 128), 256, GEMM_SMEM>>>(bqkv, nullptr);

    // 2) causal flash attention (tensor cores) -> g_att (tf32, perm)
    attn_mma<<<dim3(T_ / 64, B_ * H_), 128, ATT_SMEM>>>();

    // 3) output projection
    gemm_tc<C_, 1><<<dim3(C_ / 128, M_TOT / 128), 256, GEMM_SMEM>>>(bproj, out);
}

// round 7
// speedup vs baseline: 3.6090x; 2.1944x over previous
#include <cuda_runtime.h>
#include <cuda_fp16.h>
#include <math.h>
#include <cstdint>

#define B_ 64
#define T_ 256
#define C_ 384
#define H_ 6
#define D_ 64
#define K_ 384
#define M_TOT (B_*T_)   // 16384
#define KP2 (K_/2)      // 192 u32 (half2) per row

// ------------------------- scratch (no allocation) -------------------------
__device__ uint32_t g_xh[M_TOT*KP2];        // x, fp16 pairs, pair-slotted
__device__ uint32_t g_wqh[3*C_*KP2];        // Wqkv^T [n][pair-slot(k)]
__device__ uint32_t g_wph[C_*KP2];          // Wproj^T
__device__ uint32_t g_atth[M_TOT*KP2];      // attention out, fp16 slotted
__device__ uint32_t g_qh[B_*H_*T_*(D_/2)];  // [b,h,t][d-pair slot]
__device__ uint32_t g_kh[B_*H_*T_*(D_/2)];
__device__ uint32_t g_vh[B_*H_*T_*(D_/2)];
__device__ uint32_t g_vt[B_*H_*D_*(T_/2)];  // V^T: [b,h,d][key-pair slot]

// ------------------------- helpers -------------------------
// slot of pair p within its group of 8 pairs (16 k): p(b2b1b0) -> (b1b0b2)
__device__ __forceinline__ int slot8(int p) { return (p & ~7) | (((p & 3) << 1) | ((p >> 2) & 1)); }
__device__ __forceinline__ int inv8(int s)  { return ((s & 1) << 2) | ((s >> 1) & 3); }   // low-3 inverse

__device__ __forceinline__ uint32_t pack2f(float a, float b) {
    __half2 h = __floats2half2_rn(a, b);
    return *reinterpret_cast<uint32_t*>(&h);
}
__device__ __forceinline__ uint32_t pack2h(__half a, __half b) {
    __half2 h = __halves2half2(a, b);
    return *reinterpret_cast<uint32_t*>(&h);
}
__device__ __forceinline__ void mma_f16(float c[4], const uint32_t a[4], uint32_t b0, uint32_t b1) {
    asm volatile(
        "mma.sync.aligned.m16n8k16.row.col.f32.f16.f16.f32 "
        "{%0,%1,%2,%3}, {%4,%5,%6,%7}, {%8,%9}, {%0,%1,%2,%3};"
        : "+f"(c[0]), "+f"(c[1]), "+f"(c[2]), "+f"(c[3])
        : "r"(a[0]), "r"(a[1]), "r"(a[2]), "r"(a[3]), "r"(b0), "r"(b1));
}
#define CP16(dst, src) asm volatile("cp.async.cg.shared.global [%0], [%1], 16;" :: "r"(dst), "l"(src) : "memory")
#define CP_COMMIT()    asm volatile("cp.async.commit_group;" ::: "memory")
#define CP_WAIT1()     asm volatile("cp.async.wait_group 1;" ::: "memory")
#define CP_WAIT0()     asm volatile("cp.async.wait_group 0;" ::: "memory")
__device__ __forceinline__ uint32_t smem_u32(const void* p) {
    uint32_t a;
    asm("{ .reg .u64 t; cvta.to.shared.u64 t, %1; cvt.u32.u64 %0, t; }" : "=r"(a) : "l"(p));
    return a;
}

// ------------------------- conversion kernels -------------------------
// x: 16 floats (8 pairs) per thread -> slotted half2
__global__ __launch_bounds__(256) void conv_x(const float* __restrict__ x) {
    const int gi = blockIdx.x * 256 + threadIdx.x;
    const float* s = x + (size_t)gi * 16;
    float4 v0 = *(const float4*)(s);
    float4 v1 = *(const float4*)(s + 4);
    float4 v2 = *(const float4*)(s + 8);
    float4 v3 = *(const float4*)(s + 12);
    uint32_t* o = g_xh + (size_t)gi * 8;
    o[0] = pack2f(v0.x, v0.y); o[2] = pack2f(v0.z, v0.w);
    o[4] = pack2f(v1.x, v1.y); o[6] = pack2f(v1.z, v1.w);
    o[1] = pack2f(v2.x, v2.y); o[3] = pack2f(v2.z, v2.w);
    o[5] = pack2f(v3.x, v3.y); o[7] = pack2f(v3.z, v3.w);
}

// W[k][n] -> out[n][slot(k-pair)]
template<int WHICH>
__global__ void conv_w(const float* __restrict__ W, int N) {
    __shared__ float t[32][33];
    uint32_t* out = (WHICH == 0) ? g_wqh : g_wph;
    const int nx = blockIdx.x * 32, kx = blockIdx.y * 32;
    const int x = threadIdx.x, y = threadIdx.y;
    #pragma unroll
    for (int i = y; i < 32; i += 8) t[i][x] = W[(size_t)(kx + i) * N + nx + x];
    __syncthreads();
    #pragma unroll
    for (int i = y; i < 16; i += 8) {
        const int slot = slot8(i);
        out[(size_t)(nx + x) * KP2 + kx / 2 + slot] = pack2f(t[2 * i][x], t[2 * i + 1][x]);
    }
}

// V transpose: g_vh [t][d-slot] -> g_vt [d][key-pair slot]
__global__ __launch_bounds__(256) void conv_v() {
    __shared__ uint32_t sm[64][33];
    const int bh = blockIdx.x >> 2, kt = blockIdx.x & 3;
    const int tid = threadIdx.x;
    const uint32_t* src = g_vh + (size_t)(bh * T_ + kt * 64) * 32;
    #pragma unroll
    for (int j = 0; j < 8; j++) {
        const int u = tid + j * 256;
        sm[u >> 5][u & 31] = src[(u >> 5) * 32 + (u & 31)];
    }
    __syncthreads();
    #pragma unroll
    for (int j = 0; j < 8; j++) {
        const int u = tid + j * 256;
        const int d = u >> 5, kidx = u & 31;
        const int kp = (kidx & 24) | inv8(kidx & 7);       // local key-pair for this slot
        const int pd = d >> 1;
        const int s = slot8(pd);                           // gmem slot holding d
        __half2 a = *reinterpret_cast<__half2*>(&sm[2 * kp][s]);
        __half2 b = *reinterpret_cast<__half2*>(&sm[2 * kp + 1][s]);
        uint32_t val = (d & 1) ? pack2h(__high2half(a), __high2half(b))
                               : pack2h(__low2half(a), __low2half(b));
        g_vt[((size_t)bh * 64 + d) * (T_ / 2) + kt * 32 + kidx] = val;
    }
}

// ---------------------------------------------------------------------------
// fp16 MMA GEMM, cp.async 3-stage. 128x128 tile, BK=32 (16 pairs), 256 thr.
// 8 warps 2(M)x4(N), warp tile 64x32. smem pitch 24 u32 (conflict-free).
// MODE 0: A=g_xh, B=g_wqh, scatter fp16 q/k/v.  MODE 1: A=g_atth, B=g_wph.
// ---------------------------------------------------------------------------
#define GP 24
#define STG (256 * GP * 4)       // 24576 B per stage (A 128 rows + B 128 rows)
#define GEMM_SMEM (3 * STG)      // 73728

template<int N, int MODE>
__global__ __launch_bounds__(256) void gemm_h(const float* __restrict__ bias,
                                              float* __restrict__ out) {
    extern __shared__ char smem[];
    const uint32_t sb = smem_u32(smem);
    const uint32_t* sm = (const uint32_t*)smem;

    const int tid = threadIdx.x;
    const int wid = tid >> 5;
    const int lane = tid & 31;
    const int r = lane >> 2, q = lane & 3;
    const int m0 = blockIdx.y * 128;
    const int n0 = blockIdx.x * 128;
    const int wm = (wid & 1) * 64;
    const int wn = (wid >> 1) * 32;

    const uint32_t* Ap = (MODE == 0) ? g_xh : g_atth;
    const uint32_t* Bp = (MODE == 0) ? g_wqh : g_wph;

    auto load_stage = [&](int kc, int st) {
        #pragma unroll
        for (int j = 0; j < 4; j++) {
            const int c = tid + j * 256;
            const int row = c >> 2, seg = c & 3;
            const uint32_t* src = (row < 128)
                ? Ap + (size_t)(m0 + row) * KP2 + kc * 16 + seg * 4
                : Bp + (size_t)(n0 + row - 128) * KP2 + kc * 16 + seg * 4;
            CP16(sb + st * STG + row * (GP * 4) + seg * 16, src);
        }
        CP_COMMIT();
    };

    float acc[4][4][4] = {};
    load_stage(0, 0);
    load_stage(1, 1);

    const int NCH = K_ / 32;   // 12
    for (int kc = 0; kc < NCH; kc++) {
        const int st = kc % 3;
        if (kc < NCH - 1) CP_WAIT1(); else CP_WAIT0();
        __syncthreads();
        if (kc + 2 < NCH) load_stage(kc + 2, (kc + 2) % 3);

        const uint32_t* As = sm + st * (STG / 4);
        const uint32_t* Bs = As + 128 * GP;
        #pragma unroll
        for (int ks = 0; ks < 2; ks++) {
            const int koff = ks * 8 + 2 * q;
            uint32_t af[4][4];
            #pragma unroll
            for (int mt = 0; mt < 4; mt++) {
                const int mr = wm + mt * 16 + r;
                uint2 a0 = *(const uint2*)&As[mr * GP + koff];
                uint2 a1 = *(const uint2*)&As[(mr + 8) * GP + koff];
                af[mt][0] = a0.x; af[mt][1] = a1.x; af[mt][2] = a0.y; af[mt][3] = a1.y;
            }
            uint2 bf[4];
            #pragma unroll
            for (int nt = 0; nt < 4; nt++)
                bf[nt] = *(const uint2*)&Bs[(wn + nt * 8 + r) * GP + koff];
            #pragma unroll
            for (int mt = 0; mt < 4; mt++)
                #pragma unroll
                for (int nt = 0; nt < 4; nt++)
                    mma_f16(acc[mt][nt], af[mt], bf[nt].x, bf[nt].y);
        }
    }

    // ---- epilogue ----
    #pragma unroll
    for (int mt = 0; mt < 4; mt++) {
        #pragma unroll
        for (int nt = 0; nt < 4; nt++) {
            const int row0 = m0 + wm + mt * 16 + r;
            const int row1 = row0 + 8;
            const int col = n0 + wn + nt * 8 + q * 2;
            const float b0 = bias[col], b1 = bias[col + 1];
            const float v00 = acc[mt][nt][0] + b0, v01 = acc[mt][nt][1] + b1;
            const float v10 = acc[mt][nt][2] + b0, v11 = acc[mt][nt][3] + b1;
            if (MODE == 0) {
                const int which = n0 / C_;
                const int rem = col - which * C_;
                const int h = rem >> 6, d = rem & 63;
                const int pd = d >> 1;
                const int slot = slot8(pd);
                uint32_t* qkv = (which == 0) ? g_qh : (which == 1) ? g_kh : g_vh;
                const int b0i = row0 >> 8, t0 = row0 & 255;
                const int b1i = row1 >> 8, t1 = row1 & 255;
                qkv[((size_t)(b0i * H_ + h) * T_ + t0) * 32 + slot] = pack2f(v00, v01);
                qkv[((size_t)(b1i * H_ + h) * T_ + t1) * 32 + slot] = pack2f(v10, v11);
            } else {
                *(float2*)&out[(size_t)row0 * N + col] = make_float2(v00, v01);
                *(float2*)&out[(size_t)row1 * N + col] = make_float2(v10, v11);
            }
        }
    }
}

// ---------------------------------------------------------------------------
// Flash attention, fp16 mma. grid=(T/64, B*H), 128 threads (4 warps).
// Br=64, Bc=64. All tiles arrive via cp.async (Q/K from g_qh/g_kh, V from g_vt).
// smem pitch 40 u32 (conflict-free fragment loads).
// ---------------------------------------------------------------------------
#define AP 40

__global__ __launch_bounds__(128) void attn_h() {
    __shared__ uint32_t Qs[64 * AP], Ks[64 * AP], Vt[64 * AP], Ps[64 * AP];

    const int tid = threadIdx.x;
    const int w = tid >> 5;
    const int lane = tid & 31;
    const int r = lane >> 2, q = lane & 3;
    const int qt = blockIdx.x;
    const int bh = blockIdx.y;
    const int wrow = w * 16;

    const uint32_t sQ = smem_u32(Qs), sK = smem_u32(Ks), sV = smem_u32(Vt);

    // Q tile: 64 rows x 32 u32, cp.async
    {
        const uint32_t* src = g_qh + (size_t)(bh * T_ + qt * 64) * 32;
        #pragma unroll
        for (int j = 0; j < 4; j++) {
            const int c = tid + j * 128;
            const int row = c >> 3, seg = c & 7;
            CP16(sQ + row * (AP * 4) + seg * 16, src + row * 32 + seg * 4);
        }
        CP_COMMIT();
    }

    float m0 = -INFINITY, m1 = -INFINITY, l0 = 0.f, l1 = 0.f;
    float Oacc[8][4] = {};

    for (int jt = 0; jt <= qt; jt++) {
        __syncthreads();   // prior iteration done with Ks/Vt
        {
            const uint32_t* ksrc = g_kh + (size_t)(bh * T_ + jt * 64) * 32;
            const uint32_t* vsrc = g_vt + (size_t)bh * 64 * (T_ / 2) + jt * 32;
            #pragma unroll
            for (int j = 0; j < 4; j++) {
                const int c = tid + j * 128;
                const int row = c >> 3, seg = c & 7;
                CP16(sK + row * (AP * 4) + seg * 16, ksrc + row * 32 + seg * 4);
                CP16(sV + row * (AP * 4) + seg * 16, vsrc + (size_t)row * (T_ / 2) + seg * 4);
            }
            CP_COMMIT();
        }
        CP_WAIT0();
        __syncthreads();

        // ---- S = Q K^T ----
        float S[8][4] = {};
        #pragma unroll
        for (int ks = 0; ks < 4; ks++) {
            const int koff = ks * 8 + 2 * q;
            uint2 a0 = *(const uint2*)&Qs[(wrow + r) * AP + koff];
            uint2 a1 = *(const uint2*)&Qs[(wrow + r + 8) * AP + koff];
            uint32_t af[4] = {a0.x, a1.x, a0.y, a1.y};
            #pragma unroll
            for (int nt = 0; nt < 8; nt++) {
                uint2 b = *(const uint2*)&Ks[(nt * 8 + r) * AP + koff];
                mma_f16(S[nt], af, b.x, b.y);
            }
        }

        // ---- scale + causal mask ----
        #pragma unroll
        for (int nt = 0; nt < 8; nt++)
            #pragma unroll
            for (int c = 0; c < 4; c++)
                S[nt][c] *= 0.125f;
        if (jt == qt) {
            const int ir0 = wrow + r, ir1 = wrow + r + 8;
            #pragma unroll
            for (int nt = 0; nt < 8; nt++) {
                const int jc = nt * 8 + 2 * q;
                if (jc > ir0)     S[nt][0] = -INFINITY;
                if (jc + 1 > ir0) S[nt][1] = -INFINITY;
                if (jc > ir1)     S[nt][2] = -INFINITY;
                if (jc + 1 > ir1) S[nt][3] = -INFINITY;
            }
        }

        // ---- online softmax ----
        float mx0 = -INFINITY, mx1 = -INFINITY;
        #pragma unroll
        for (int nt = 0; nt < 8; nt++) {
            mx0 = fmaxf(mx0, fmaxf(S[nt][0], S[nt][1]));
            mx1 = fmaxf(mx1, fmaxf(S[nt][2], S[nt][3]));
        }
        mx0 = fmaxf(mx0, __shfl_xor_sync(0xffffffffu, mx0, 1));
        mx0 = fmaxf(mx0, __shfl_xor_sync(0xffffffffu, mx0, 2));
        mx1 = fmaxf(mx1, __shfl_xor_sync(0xffffffffu, mx1, 1));
        mx1 = fmaxf(mx1, __shfl_xor_sync(0xffffffffu, mx1, 2));
        const float mn0 = fmaxf(m0, mx0), mn1 = fmaxf(m1, mx1);
        const float al0 = __expf(m0 - mn0), al1 = __expf(m1 - mn1);
        float s0 = 0.f, s1 = 0.f;
        #pragma unroll
        for (int nt = 0; nt < 8; nt++) {
            float p0 = __expf(S[nt][0] - mn0);
            float p1 = __expf(S[nt][1] - mn0);
            float p2 = __expf(S[nt][2] - mn1);
            float p3 = __expf(S[nt][3] - mn1);
            s0 += p0 + p1; s1 += p2 + p3;
            const int slot = (nt >> 1) * 8 + (q << 1) + (nt & 1);
            Ps[(wrow + r) * AP + slot] = pack2f(p0, p1);
            Ps[(wrow + r + 8) * AP + slot] = pack2f(p2, p3);
        }
        s0 += __shfl_xor_sync(0xffffffffu, s0, 1);
        s0 += __shfl_xor_sync(0xffffffffu, s0, 2);
        s1 += __shfl_xor_sync(0xffffffffu, s1, 1);
        s1 += __shfl_xor_sync(0xffffffffu, s1, 2);
        l0 = l0 * al0 + s0; l1 = l1 * al1 + s1;
        m0 = mn0; m1 = mn1;
        #pragma unroll
        for (int nt = 0; nt < 8; nt++) {
            Oacc[nt][0] *= al0; Oacc[nt][1] *= al0;
            Oacc[nt][2] *= al1; Oacc[nt][3] *= al1;
        }
        __syncwarp();

        // ---- O += P V ----
        #pragma unroll
        for (int ks = 0; ks < 4; ks++) {
            const int koff = ks * 8 + 2 * q;
            uint2 a0 = *(const uint2*)&Ps[(wrow + r) * AP + koff];
            uint2 a1 = *(const uint2*)&Ps[(wrow + r + 8) * AP + koff];
            uint32_t af[4] = {a0.x, a1.x, a0.y, a1.y};
            #pragma unroll
            for (int nt = 0; nt < 8; nt++) {
                uint2 b = *(const uint2*)&Vt[(nt * 8 + r) * AP + koff];
                mma_f16(Oacc[nt], af, b.x, b.y);
            }
        }
    }

    // ---- epilogue: normalize, write g_atth fp16 slotted ----
    const float li0 = 1.f / l0, li1 = 1.f / l1;
    const int b = bh / H_;
    const int h = bh - b * H_;
    const int row0 = qt * 64 + wrow + r;
    const int row1 = row0 + 8;
    uint32_t* o0 = g_atth + (size_t)(b * T_ + row0) * KP2 + h * 32;
    uint32_t* o1 = g_atth + (size_t)(b * T_ + row1) * KP2 + h * 32;
    #pragma unroll
    for (int nt = 0; nt < 8; nt++) {
        const int slot = (nt >> 1) * 8 + (q << 1) + (nt & 1);
        o0[slot] = pack2f(Oacc[nt][0] * li0, Oacc[nt][1] * li0);
        o1[slot] = pack2f(Oacc[nt][2] * li1, Oacc[nt][3] * li1);
    }
}

// ---------------------------------------------------------------------------
extern "C" void kernel_launch(void* const* d_in, const int* in_sizes, int n_in,
                              void* d_out, int out_size) {
    const float* x     = (const float*)d_in[0];
    const float* Wqkv  = (const float*)d_in[1];
    const float* bqkv  = (const float*)d_in[2];
    const float* Wproj = (const float*)d_in[3];
    const float* bproj = (const float*)d_in[4];
    float* out = (float*)d_out;

    cudaFuncSetAttribute(gemm_h<3 * C_, 0>, cudaFuncAttributeMaxDynamicSharedMemorySize, GEMM_SMEM);
    cudaFuncSetAttribute(gemm_h<C_, 1>,     cudaFuncAttributeMaxDynamicSharedMemorySize, GEMM_SMEM);

    // 0) fp16 conversions
    conv_x<<<M_TOT * K_ / 16 / 256, 256>>>(x);
    conv_w<0><<<dim3(3 * C_ / 32, K_ / 32), dim3(32, 8)>>>(Wqkv, 3 * C_);
    conv_w<1><<<dim3(C_ / 32, K_ / 32), dim3(32, 8)>>>(Wproj, C_);

    // 1) QKV projection -> fp16 q/k/v
    gemm_h<3 * C_, 0><<<dim3(3 * C_ / 128, M_TOT / 128), 256, GEMM_SMEM>>>(bqkv, nullptr);

    // 1b) V transpose for PV mma
    conv_v<<<B_ * H_ * 4, 256>>>();

    // 2) causal flash attention (fp16 tensor cores)
    attn_h<<<dim3(T_ / 64, B_ * H_), 128>>>();

    // 3) output projection
    gemm_h<C_, 1><<<dim3(C_ / 128, M_TOT / 128), 256, GEMM_SMEM>>>(bproj, out);
}

// round 10
// speedup vs baseline: 3.7923x; 1.0508x over previous
#include <cuda_runtime.h>
#include <cuda_fp16.h>
#include <math.h>
#include <cstdint>

#define B_ 64
#define T_ 256
#define C_ 384
#define H_ 6
#define D_ 64
#define K_ 384
#define M_TOT (B_*T_)   // 16384
#define KP2 (K_/2)      // 192 u32 (half2) per row

// ------------------------- scratch (no allocation) -------------------------
__device__ uint32_t g_xh[M_TOT*KP2];        // x, fp16 pairs, pair-slotted
__device__ uint32_t g_wqh[3*C_*KP2];        // Wqkv^T [n][pair-slot(k)]
__device__ uint32_t g_wph[C_*KP2];          // Wproj^T
__device__ uint32_t g_atth[M_TOT*KP2];      // attention out, fp16 slotted
__device__ uint32_t g_qh[B_*H_*T_*(D_/2)];  // [b,h,t][d-pair slot]
__device__ uint32_t g_kh[B_*H_*T_*(D_/2)];
__device__ uint32_t g_vh[B_*H_*T_*(D_/2)];
__device__ uint32_t g_vt[B_*H_*D_*(T_/2)];  // V^T: [b,h,d][key-pair slot]

// ------------------------- helpers -------------------------
__device__ __forceinline__ int slot8(int p) { return (p & ~7) | (((p & 3) << 1) | ((p >> 2) & 1)); }
__device__ __forceinline__ int inv8(int s)  { return ((s & 1) << 2) | ((s >> 1) & 3); }

__device__ __forceinline__ uint32_t pack2f(float a, float b) {
    __half2 h = __floats2half2_rn(a, b);
    return *reinterpret_cast<uint32_t*>(&h);
}
__device__ __forceinline__ uint32_t pack2h(__half a, __half b) {
    __half2 h = __halves2half2(a, b);
    return *reinterpret_cast<uint32_t*>(&h);
}
__device__ __forceinline__ void mma_f16(float c[4], const uint32_t a[4], uint32_t b0, uint32_t b1) {
    asm volatile(
        "mma.sync.aligned.m16n8k16.row.col.f32.f16.f16.f32 "
        "{%0,%1,%2,%3}, {%4,%5,%6,%7}, {%8,%9}, {%0,%1,%2,%3};"
        : "+f"(c[0]), "+f"(c[1]), "+f"(c[2]), "+f"(c[3])
        : "r"(a[0]), "r"(a[1]), "r"(a[2]), "r"(a[3]), "r"(b0), "r"(b1));
}
#define CP16(dst, src) asm volatile("cp.async.cg.shared.global [%0], [%1], 16;" :: "r"(dst), "l"(src) : "memory")
#define CP_COMMIT()    asm volatile("cp.async.commit_group;" ::: "memory")
#define CP_WAIT1()     asm volatile("cp.async.wait_group 1;" ::: "memory")
#define CP_WAIT0()     asm volatile("cp.async.wait_group 0;" ::: "memory")
__device__ __forceinline__ uint32_t smem_u32(const void* p) {
    uint32_t a;
    asm("{ .reg .u64 t; cvta.to.shared.u64 t, %1; cvt.u32.u64 %0, t; }" : "=r"(a) : "l"(p));
    return a;
}

// ------------------------- conversion kernels -------------------------
__global__ __launch_bounds__(256) void conv_x(const float* __restrict__ x) {
    const int gi = blockIdx.x * 256 + threadIdx.x;
    const float* s = x + (size_t)gi * 16;
    float4 v0 = *(const float4*)(s);
    float4 v1 = *(const float4*)(s + 4);
    float4 v2 = *(const float4*)(s + 8);
    float4 v3 = *(const float4*)(s + 12);
    uint32_t* o = g_xh + (size_t)gi * 8;
    o[0] = pack2f(v0.x, v0.y); o[2] = pack2f(v0.z, v0.w);
    o[4] = pack2f(v1.x, v1.y); o[6] = pack2f(v1.z, v1.w);
    o[1] = pack2f(v2.x, v2.y); o[3] = pack2f(v2.z, v2.w);
    o[5] = pack2f(v3.x, v3.y); o[7] = pack2f(v3.z, v3.w);
}

template<int WHICH>
__global__ void conv_w(const float* __restrict__ W, int N) {
    __shared__ float t[32][33];
    uint32_t* out = (WHICH == 0) ? g_wqh : g_wph;
    const int nx = blockIdx.x * 32, kx = blockIdx.y * 32;
    const int x = threadIdx.x, y = threadIdx.y;
    #pragma unroll
    for (int i = y; i < 32; i += 8) t[i][x] = W[(size_t)(kx + i) * N + nx + x];
    __syncthreads();
    #pragma unroll
    for (int i = y; i < 16; i += 8) {
        const int slot = slot8(i);
        out[(size_t)(nx + x) * KP2 + kx / 2 + slot] = pack2f(t[2 * i][x], t[2 * i + 1][x]);
    }
}

__global__ __launch_bounds__(256) void conv_v() {
    __shared__ uint32_t sm[64][33];
    const int bh = blockIdx.x >> 2, kt = blockIdx.x & 3;
    const int tid = threadIdx.x;
    const uint32_t* src = g_vh + (size_t)(bh * T_ + kt * 64) * 32;
    #pragma unroll
    for (int j = 0; j < 8; j++) {
        const int u = tid + j * 256;
        sm[u >> 5][u & 31] = src[(u >> 5) * 32 + (u & 31)];
    }
    __syncthreads();
    #pragma unroll
    for (int j = 0; j < 8; j++) {
        const int u = tid + j * 256;
        const int d = u >> 5, kidx = u & 31;
        const int kp = (kidx & 24) | inv8(kidx & 7);
        const int pd = d >> 1;
        const int s = slot8(pd);
        __half2 a = *reinterpret_cast<__half2*>(&sm[2 * kp][s]);
        __half2 b = *reinterpret_cast<__half2*>(&sm[2 * kp + 1][s]);
        uint32_t val = (d & 1) ? pack2h(__high2half(a), __high2half(b))
                               : pack2h(__low2half(a), __low2half(b));
        g_vt[((size_t)bh * 64 + d) * (T_ / 2) + kt * 32 + kidx] = val;
    }
}

// ---------------------------------------------------------------------------
// fp16 MMA GEMM, cp.async 3-stage. Block 128(M)x64(N), BK=32, 256 threads.
// 8 warps 4(M)x2(N), warp tile 32x32 (acc 32 regs) -> 3 CTAs/SM target.
// MODE 0: A=g_xh, B=g_wqh, scatter fp16 q/k/v.  MODE 1: A=g_atth, B=g_wph.
// ---------------------------------------------------------------------------
#define GP 24
#define STG (192 * GP * 4)       // 18432 B/stage: A 128 rows + B 64 rows
#define GEMM_SMEM (3 * STG)      // 55296

template<int N, int MODE>
__global__ __launch_bounds__(256, 3) void gemm_h(const float* __restrict__ bias,
                                                 float* __restrict__ out) {
    extern __shared__ char smem[];
    const uint32_t sb = smem_u32(smem);
    const uint32_t* sm = (const uint32_t*)smem;

    const int tid = threadIdx.x;
    const int wid = tid >> 5;
    const int lane = tid & 31;
    const int r = lane >> 2, q = lane & 3;
    const int m0 = blockIdx.y * 128;
    const int n0 = blockIdx.x * 64;
    const int wm = (wid & 3) * 32;
    const int wn = (wid >> 2) * 32;

    const uint32_t* Ap = (MODE == 0) ? g_xh : g_atth;
    const uint32_t* Bp = (MODE == 0) ? g_wqh : g_wph;

    auto load_stage = [&](int kc, int st) {
        #pragma unroll
        for (int j = 0; j < 3; j++) {
            const int c = tid + j * 256;
            const int row = c >> 2, seg = c & 3;
            const uint32_t* src = (row < 128)
                ? Ap + (size_t)(m0 + row) * KP2 + kc * 16 + seg * 4
                : Bp + (size_t)(n0 + row - 128) * KP2 + kc * 16 + seg * 4;
            CP16(sb + st * STG + row * (GP * 4) + seg * 16, src);
        }
        CP_COMMIT();
    };

    float acc[2][4][4] = {};
    load_stage(0, 0);
    load_stage(1, 1);

    const int NCH = K_ / 32;   // 12
    for (int kc = 0; kc < NCH; kc++) {
        const int st = kc % 3;
        if (kc < NCH - 1) CP_WAIT1(); else CP_WAIT0();
        __syncthreads();
        if (kc + 2 < NCH) load_stage(kc + 2, (kc + 2) % 3);

        const uint32_t* As = sm + st * (STG / 4);
        const uint32_t* Bs = As + 128 * GP;
        #pragma unroll
        for (int ks = 0; ks < 2; ks++) {
            const int koff = ks * 8 + 2 * q;
            uint32_t af[2][4];
            #pragma unroll
            for (int mt = 0; mt < 2; mt++) {
                const int mr = wm + mt * 16 + r;
                uint2 a0 = *(const uint2*)&As[mr * GP + koff];
                uint2 a1 = *(const uint2*)&As[(mr + 8) * GP + koff];
                af[mt][0] = a0.x; af[mt][1] = a1.x; af[mt][2] = a0.y; af[mt][3] = a1.y;
            }
            uint2 bf[4];
            #pragma unroll
            for (int nt = 0; nt < 4; nt++)
                bf[nt] = *(const uint2*)&Bs[(wn + nt * 8 + r) * GP + koff];
            #pragma unroll
            for (int mt = 0; mt < 2; mt++)
                #pragma unroll
                for (int nt = 0; nt < 4; nt++)
                    mma_f16(acc[mt][nt], af[mt], bf[nt].x, bf[nt].y);
        }
    }

    // ---- epilogue ----
    #pragma unroll
    for (int mt = 0; mt < 2; mt++) {
        #pragma unroll
        for (int nt = 0; nt < 4; nt++) {
            const int row0 = m0 + wm + mt * 16 + r;
            const int row1 = row0 + 8;
            const int col = n0 + wn + nt * 8 + q * 2;
            const float b0 = bias[col], b1 = bias[col + 1];
            const float v00 = acc[mt][nt][0] + b0, v01 = acc[mt][nt][1] + b1;
            const float v10 = acc[mt][nt][2] + b0, v11 = acc[mt][nt][3] + b1;
            if (MODE == 0) {
                const int which = n0 / C_;
                const int rem = col - which * C_;
                const int h = rem >> 6, d = rem & 63;
                const int slot = slot8(d >> 1);
                uint32_t* qkv = (which == 0) ? g_qh : (which == 1) ? g_kh : g_vh;
                const int b0i = row0 >> 8, t0 = row0 & 255;
                const int b1i = row1 >> 8, t1 = row1 & 255;
                qkv[((size_t)(b0i * H_ + h) * T_ + t0) * 32 + slot] = pack2f(v00, v01);
                qkv[((size_t)(b1i * H_ + h) * T_ + t1) * 32 + slot] = pack2f(v10, v11);
            } else {
                *(float2*)&out[(size_t)row0 * N + col] = make_float2(v00, v01);
                *(float2*)&out[(size_t)row1 * N + col] = make_float2(v10, v11);
            }
        }
    }
}

// ---------------------------------------------------------------------------
// Flash attention, fp16 mma (unchanged from round 7 passing kernel).
// grid=(T/64, B*H), 128 threads (4 warps). Br=64, Bc=64.
// ---------------------------------------------------------------------------
#define AP 40

__global__ __launch_bounds__(128) void attn_h() {
    __shared__ uint32_t Qs[64 * AP], Ks[64 * AP], Vt[64 * AP], Ps[64 * AP];

    const int tid = threadIdx.x;
    const int w = tid >> 5;
    const int lane = tid & 31;
    const int r = lane >> 2, q = lane & 3;
    const int qt = blockIdx.x;
    const int bh = blockIdx.y;
    const int wrow = w * 16;

    const uint32_t sQ = smem_u32(Qs), sK = smem_u32(Ks), sV = smem_u32(Vt);

    {
        const uint32_t* src = g_qh + (size_t)(bh * T_ + qt * 64) * 32;
        #pragma unroll
        for (int j = 0; j < 4; j++) {
            const int c = tid + j * 128;
            const int row = c >> 3, seg = c & 7;
            CP16(sQ + row * (AP * 4) + seg * 16, src + row * 32 + seg * 4);
        }
        CP_COMMIT();
    }

    float m0 = -INFINITY, m1 = -INFINITY, l0 = 0.f, l1 = 0.f;
    float Oacc[8][4] = {};

    for (int jt = 0; jt <= qt; jt++) {
        __syncthreads();
        {
            const uint32_t* ksrc = g_kh + (size_t)(bh * T_ + jt * 64) * 32;
            const uint32_t* vsrc = g_vt + (size_t)bh * 64 * (T_ / 2) + jt * 32;
            #pragma unroll
            for (int j = 0; j < 4; j++) {
                const int c = tid + j * 128;
                const int row = c >> 3, seg = c & 7;
                CP16(sK + row * (AP * 4) + seg * 16, ksrc + row * 32 + seg * 4);
                CP16(sV + row * (AP * 4) + seg * 16, vsrc + (size_t)row * (T_ / 2) + seg * 4);
            }
            CP_COMMIT();
        }
        CP_WAIT0();
        __syncthreads();

        float S[8][4] = {};
        #pragma unroll
        for (int ks = 0; ks < 4; ks++) {
            const int koff = ks * 8 + 2 * q;
            uint2 a0 = *(const uint2*)&Qs[(wrow + r) * AP + koff];
            uint2 a1 = *(const uint2*)&Qs[(wrow + r + 8) * AP + koff];
            uint32_t af[4] = {a0.x, a1.x, a0.y, a1.y};
            #pragma unroll
            for (int nt = 0; nt < 8; nt++) {
                uint2 b = *(const uint2*)&Ks[(nt * 8 + r) * AP + koff];
                mma_f16(S[nt], af, b.x, b.y);
            }
        }

        #pragma unroll
        for (int nt = 0; nt < 8; nt++)
            #pragma unroll
            for (int c = 0; c < 4; c++)
                S[nt][c] *= 0.125f;
        if (jt == qt) {
            const int ir0 = wrow + r, ir1 = wrow + r + 8;
            #pragma unroll
            for (int nt = 0; nt < 8; nt++) {
                const int jc = nt * 8 + 2 * q;
                if (jc > ir0)     S[nt][0] = -INFINITY;
                if (jc + 1 > ir0) S[nt][1] = -INFINITY;
                if (jc > ir1)     S[nt][2] = -INFINITY;
                if (jc + 1 > ir1) S[nt][3] = -INFINITY;
            }
        }

        float mx0 = -INFINITY, mx1 = -INFINITY;
        #pragma unroll
        for (int nt = 0; nt < 8; nt++) {
            mx0 = fmaxf(mx0, fmaxf(S[nt][0], S[nt][1]));
            mx1 = fmaxf(mx1, fmaxf(S[nt][2], S[nt][3]));
        }
        mx0 = fmaxf(mx0, __shfl_xor_sync(0xffffffffu, mx0, 1));
        mx0 = fmaxf(mx0, __shfl_xor_sync(0xffffffffu, mx0, 2));
        mx1 = fmaxf(mx1, __shfl_xor_sync(0xffffffffu, mx1, 1));
        mx1 = fmaxf(mx1, __shfl_xor_sync(0xffffffffu, mx1, 2));
        const float mn0 = fmaxf(m0, mx0), mn1 = fmaxf(m1, mx1);
        const float al0 = __expf(m0 - mn0), al1 = __expf(m1 - mn1);
        float s0 = 0.f, s1 = 0.f;
        #pragma unroll
        for (int nt = 0; nt < 8; nt++) {
            float p0 = __expf(S[nt][0] - mn0);
            float p1 = __expf(S[nt][1] - mn0);
            float p2 = __expf(S[nt][2] - mn1);
            float p3 = __expf(S[nt][3] - mn1);
            s0 += p0 + p1; s1 += p2 + p3;
            const int slot = (nt >> 1) * 8 + (q << 1) + (nt & 1);
            Ps[(wrow + r) * AP + slot] = pack2f(p0, p1);
            Ps[(wrow + r + 8) * AP + slot] = pack2f(p2, p3);
        }
        s0 += __shfl_xor_sync(0xffffffffu, s0, 1);
        s0 += __shfl_xor_sync(0xffffffffu, s0, 2);
        s1 += __shfl_xor_sync(0xffffffffu, s1, 1);
        s1 += __shfl_xor_sync(0xffffffffu, s1, 2);
        l0 = l0 * al0 + s0; l1 = l1 * al1 + s1;
        m0 = mn0; m1 = mn1;
        #pragma unroll
        for (int nt = 0; nt < 8; nt++) {
            Oacc[nt][0] *= al0; Oacc[nt][1] *= al0;
            Oacc[nt][2] *= al1; Oacc[nt][3] *= al1;
        }
        __syncwarp();

        #pragma unroll
        for (int ks = 0; ks < 4; ks++) {
            const int koff = ks * 8 + 2 * q;
            uint2 a0 = *(const uint2*)&Ps[(wrow + r) * AP + koff];
            uint2 a1 = *(const uint2*)&Ps[(wrow + r + 8) * AP + koff];
            uint32_t af[4] = {a0.x, a1.x, a0.y, a1.y};
            #pragma unroll
            for (int nt = 0; nt < 8; nt++) {
                uint2 b = *(const uint2*)&Vt[(nt * 8 + r) * AP + koff];
                mma_f16(Oacc[nt], af, b.x, b.y);
            }
        }
    }

    const float li0 = 1.f / l0, li1 = 1.f / l1;
    const int b = bh / H_;
    const int h = bh - b * H_;
    const int row0 = qt * 64 + wrow + r;
    const int row1 = row0 + 8;
    uint32_t* o0 = g_atth + (size_t)(b * T_ + row0) * KP2 + h * 32;
    uint32_t* o1 = g_atth + (size_t)(b * T_ + row1) * KP2 + h * 32;
    #pragma unroll
    for (int nt = 0; nt < 8; nt++) {
        const int slot = (nt >> 1) * 8 + (q << 1) + (nt & 1);
        o0[slot] = pack2f(Oacc[nt][0] * li0, Oacc[nt][1] * li0);
        o1[slot] = pack2f(Oacc[nt][2] * li1, Oacc[nt][3] * li1);
    }
}

// ---------------------------------------------------------------------------
extern "C" void kernel_launch(void* const* d_in, const int* in_sizes, int n_in,
                              void* d_out, int out_size) {
    const float* x     = (const float*)d_in[0];
    const float* Wqkv  = (const float*)d_in[1];
    const float* bqkv  = (const float*)d_in[2];
    const float* Wproj = (const float*)d_in[3];
    const float* bproj = (const float*)d_in[4];
    float* out = (float*)d_out;

    cudaFuncSetAttribute(gemm_h<3 * C_, 0>, cudaFuncAttributeMaxDynamicSharedMemorySize, GEMM_SMEM);
    cudaFuncSetAttribute(gemm_h<C_, 1>,     cudaFuncAttributeMaxDynamicSharedMemorySize, GEMM_SMEM);

    // 0) fp16 conversions
    conv_x<<<M_TOT * K_ / 16 / 256, 256>>>(x);
    conv_w<0><<<dim3(3 * C_ / 32, K_ / 32), dim3(32, 8)>>>(Wqkv, 3 * C_);
    conv_w<1><<<dim3(C_ / 32, K_ / 32), dim3(32, 8)>>>(Wproj, C_);

    // 1) QKV projection -> fp16 q/k/v
    gemm_h<3 * C_, 0><<<dim3(3 * C_ / 64, M_TOT / 128), 256, GEMM_SMEM>>>(bqkv, nullptr);

    // 1b) V transpose for PV mma
    conv_v<<<B_ * H_ * 4, 256>>>();

    // 2) causal flash attention (fp16 tensor cores)
    attn_h<<<dim3(T_ / 64, B_ * H_), 128>>>();

    // 3) output projection
    gemm_h<C_, 1><<<dim3(C_ / 64, M_TOT / 128), 256, GEMM_SMEM>>>(bproj, out);
}